// round 5
// baseline (speedup 1.0000x reference)
#include <cuda_runtime.h>
#include <cstdint>

// ---------------- problem constants ----------------
#define NB   32
#define CI   256
#define CO   256
#define HH   56
#define WW   56
#define HWSZ (HH*WW)
#define NTAP 9

// ---------------- device scratch (no runtime alloc allowed) ----------------
// sign(x) as int8 NHWC: [n][h][w][c], 25.7 MB
__device__ uint4 g_A4[(size_t)NB * HH * WW * (CI / 16)];
// weights pre-permuted into IMMA B-fragment order:
// [kstep 72][ogrp16 16][lane 32] x 16 bytes
__device__ uint4 g_Wf4[72 * 16 * 32];

__device__ __forceinline__ uint32_t smem_u32(const void* p) {
    uint32_t a;
    asm("{ .reg .u64 t; cvta.to.shared.u64 t, %1; cvt.u32.u64 %0, t; }" : "=r"(a) : "l"(p));
    return a;
}

// ---------------- pack kernels ----------------
// sign(x): NCHW f32 -> NHWC int8 (+1/-1), via smem transpose
__global__ void pack_x_kernel(const float* __restrict__ x) {
    __shared__ char s[WW * CI];                 // [w][c], 14336 B
    const int n = blockIdx.y, h = blockIdx.x, tid = threadIdx.x;
    for (int i = tid; i < WW * CI; i += 256) {
        int c = i / WW, w = i % WW;             // coalesced over w
        float v = x[((size_t)(n * CI + c) * HH + h) * WW + w];
        s[w * CI + c] = (v >= 0.0f) ? (char)1 : (char)-1;
    }
    __syncthreads();
    uint4* dst = g_A4 + ((size_t)(n * HH + h) * WW) * (CI / 16);
    for (int i = tid; i < WW * CI / 16; i += 256) dst[i] = ((const uint4*)s)[i];
}

// sign(M) -> IMMA B-fragment order.
// For kstep (tap,chunk), o-group g (16 cols), lane:
//   bytes 0-3  = W[o0+row][c0 + kb + 0..3]          (b0 of n8 tile 0)
//   bytes 4-7  = W[o0+row][c0 + 16 + kb + 0..3]     (b1 of n8 tile 0)
//   bytes 8-11 = W[o0+8+row][c0 + kb + 0..3]        (b0 of n8 tile 1)
//   bytes 12-15= W[o0+8+row][c0 + 16 + kb + 0..3]   (b1 of n8 tile 1)
// with row = lane/4, kb = (lane%4)*4, o0 = g*16, c0 = chunk*32.
__global__ void pack_wf_kernel(const float* __restrict__ M) {
    int idx = blockIdx.x * blockDim.x + threadIdx.x;
    if (idx >= 72 * 16 * 32) return;
    const int lane  = idx & 31;
    const int grp   = (idx >> 5) & 15;
    const int kstep = idx >> 9;                 // 0..71
    const int tap   = kstep >> 3;
    const int chunk = kstep & 7;
    const int row = lane >> 2, kb = (lane & 3) * 4;
    const int o0 = grp * 16, c0 = chunk * 32;
    char b[16];
#pragma unroll
    for (int j = 0; j < 4; j++) {
        int o = o0 + ((j >> 1) ? 8 : 0) + row;
        int c = c0 + ((j & 1) ? 16 : 0) + kb;
#pragma unroll
        for (int t = 0; t < 4; t++) {
            float v = M[((size_t)o * CI + (c + t)) * NTAP + tap];
            b[j * 4 + t] = (v >= 0.0f) ? (char)1 : (char)-1;
        }
    }
    g_Wf4[idx] = *(const uint4*)b;
}

// ---------------- main IMMA conv kernel ----------------
// Block: (row-pair bx, image n, o-half bz). M=128 (2 rows x 64 padded cols),
// N=128, K=2304. A tile staged once: [4 rows][66 cols used, stride 272B][256 ch].
#define A_COL_STRIDE 272                        // 256 ch + 16 pad (bank-conflict-free ldmatrix)
#define A_TILE_BYTES (4 * 72 * A_COL_STRIDE)    // 78336
#define SMEM_BYTES   A_TILE_BYTES

extern __shared__ __align__(16) char smem[];

#define IMMA(d, a, b0, b1)                                                      \
    asm volatile("mma.sync.aligned.m16n8k32.row.col.s32.s8.s8.s32 "             \
        "{%0,%1,%2,%3}, {%4,%5,%6,%7}, {%8,%9}, {%0,%1,%2,%3};"                 \
        : "+r"((d)[0]), "+r"((d)[1]), "+r"((d)[2]), "+r"((d)[3])                \
        : "r"((a)[0]), "r"((a)[1]), "r"((a)[2]), "r"((a)[3]), "r"(b0), "r"(b1))

__global__ __launch_bounds__(256, 2)
void bconv_imma_kernel(const float* __restrict__ alpha, float* __restrict__ out) {
    const int tid = threadIdx.x, lane = tid & 31, wid = tid >> 5;
    const int warp_m = wid >> 2, warp_n = wid & 3;
    const int n = blockIdx.y, h0 = blockIdx.x * 2, bz = blockIdx.z;
    const uint32_t sA = smem_u32(smem);

    // zero A tile (covers padding cols / invalid rows), then fill valid region
    for (int i = tid; i < A_TILE_BYTES / 16; i += 256)
        ((uint4*)smem)[i] = make_uint4(0, 0, 0, 0);
    __syncthreads();
    for (int i = tid; i < 4 * WW * (CI / 16); i += 256) {
        int u  = i & 15;
        int iw = (i >> 4) % WW;
        int rp = i / (16 * WW);                 // 0..3
        int h  = h0 - 1 + rp;
        if (h >= 0 && h < HH) {
            uint4 v = g_A4[((size_t)(n * HH + h) * WW + iw) * 16 + u];
            *(uint4*)(smem + (rp * 72 + iw + 1) * A_COL_STRIDE + u * 16) = v;
        }
    }
    __syncthreads();

    // ---- main K loop: 72 k-steps (9 taps x 8 ch-chunks) ----
    const uint4* pB = g_Wf4 + (bz * 8 + warp_n * 2) * 32 + lane;
    uint4 bc0 = pB[0], bc1 = pB[32];
    uint32_t abase[4];
    int d[16][4];
#pragma unroll
    for (int t = 0; t < 16; t++)
#pragma unroll
        for (int c = 0; c < 4; c++) d[t][c] = 0;

#pragma unroll 1
    for (int k = 0; k < 72; k++) {
        const int tap = k >> 3, ch = k & 7;
        if (ch == 0) {
            const int dy  = tap / 3 - 1;
            const int dxp = tap % 3;            // dx + 1
#pragma unroll
            for (int t = 0; t < 4; t++)
                abase[t] = sA + (uint32_t)(((warp_m + dy + 1) * 72 + t * 16 +
                                            (lane & 15) + dxp) * A_COL_STRIDE) +
                           ((lane >> 4) << 4);
        }
        // prefetch next B frags
        uint4 bn0 = bc0, bn1 = bc1;
        if (k < 71) { bn0 = pB[(k + 1) * 512]; bn1 = pB[(k + 1) * 512 + 32]; }

        uint32_t a[16];
#pragma unroll
        for (int t = 0; t < 4; t++) {
            asm volatile("ldmatrix.sync.aligned.m8n8.x4.shared.b16 {%0,%1,%2,%3}, [%4];"
                : "=r"(a[4 * t]), "=r"(a[4 * t + 1]), "=r"(a[4 * t + 2]), "=r"(a[4 * t + 3])
                : "r"(abase[t] + ch * 32));
        }
#pragma unroll
        for (int t = 0; t < 4; t++) {
            IMMA(d[t * 4 + 0], a + 4 * t, bc0.x, bc0.y);
            IMMA(d[t * 4 + 1], a + 4 * t, bc0.z, bc0.w);
            IMMA(d[t * 4 + 2], a + 4 * t, bc1.x, bc1.y);
            IMMA(d[t * 4 + 3], a + 4 * t, bc1.z, bc1.w);
        }
        bc0 = bn0; bc1 = bn1;
    }

    // ---- epilogue: transpose via smem (reuse A tile), coalesced stores ----
    __syncthreads();                            // all warps done reading A tile
    float* sw = (float*)smem + wid * (32 * 65); // 8320 B per warp
#pragma unroll
    for (int t16 = 0; t16 < 4; t16++)
#pragma unroll
        for (int t8 = 0; t8 < 4; t8++)
#pragma unroll
            for (int c = 0; c < 4; c++) {
                int w = t16 * 16 + (lane >> 2) + ((c & 2) ? 8 : 0);
                int o = t8 * 8 + (lane & 3) * 2 + (c & 1);
                sw[o * 65 + w] = (float)d[t16 * 4 + t8][c];
            }
    __syncwarp();

    const int h   = h0 + warp_m;
    const int og0 = bz * 128 + warp_n * 32;
    for (int ol = 0; ol < 32; ol++) {
        float av = __ldg(&alpha[og0 + ol]);
        size_t rb = ((size_t)(n * CO + og0 + ol)) * HWSZ + (size_t)h * WW;
        out[rb + lane] = av * sw[ol * 65 + lane];
        if (lane < WW - 32)
            out[rb + 32 + lane] = av * sw[ol * 65 + 32 + lane];
    }
}

// ---------------- launch ----------------
extern "C" void kernel_launch(void* const* d_in, const int* in_sizes, int n_in,
                              void* d_out, int out_size) {
    const float* x     = (const float*)d_in[0];   // (32,256,56,56)
    const float* M     = (const float*)d_in[1];   // (256,256,3,3)
    const float* alpha = (const float*)d_in[2];   // (256,1,1)
    float* out         = (float*)d_out;           // (32,256,56,56)

    static bool attr_set = false;
    if (!attr_set) {
        cudaFuncSetAttribute(bconv_imma_kernel,
                             cudaFuncAttributeMaxDynamicSharedMemorySize, SMEM_BYTES);
        attr_set = true;
    }

    pack_x_kernel<<<dim3(HH, NB), 256>>>(x);
    pack_wf_kernel<<<(72 * 16 * 32 + 255) / 256, 256>>>(M);
    bconv_imma_kernel<<<dim3(HH / 2, NB, 2), 256, SMEM_BYTES>>>(alpha, out);
}

// round 6
// speedup vs baseline: 1.0735x; 1.0735x over previous
#include <cuda_runtime.h>
#include <cstdint>

// ---------------- problem constants ----------------
#define NB   32
#define CI   256
#define CO   256
#define HH   56
#define WW   56
#define HWSZ (HH*WW)
#define NTAP 9

// ---------------- device scratch (no runtime alloc allowed) ----------------
// sign(x) as int8 NHWC: [n][h][w][c], 25.7 MB
__device__ uint4 g_A4[(size_t)NB * HH * WW * (CI / 16)];
// weights pre-permuted into IMMA B-fragment order:
// [kstep 72][ogrp16 16][lane 32] x 16 bytes
__device__ uint4 g_Wf4[72 * 16 * 32];

__device__ __forceinline__ uint32_t smem_u32(const void* p) {
    uint32_t a;
    asm("{ .reg .u64 t; cvta.to.shared.u64 t, %1; cvt.u32.u64 %0, t; }" : "=r"(a) : "l"(p));
    return a;
}

// ---------------- pack kernels ----------------
// sign(x): NCHW f32 -> NHWC int8 (+1/-1), via bank-conflict-free smem transpose.
// smem row stride 260 B: consecutive w -> bank+1 (conflict-free stores).
#define XS_STRIDE 260
__global__ void pack_x_kernel(const float* __restrict__ x) {
    __shared__ char s[WW * XS_STRIDE];          // 14,560 B
    const int n = blockIdx.y, h = blockIdx.x, tid = threadIdx.x;
    for (int i = tid; i < WW * CI; i += 256) {
        int w = i % WW, c = i / WW;             // coalesced over w
        float v = x[((size_t)(n * CI + c) * HH + h) * WW + w];
        s[w * XS_STRIDE + c] = (v >= 0.0f) ? (char)1 : (char)-1;
    }
    __syncthreads();
    unsigned* dst = (unsigned*)(g_A4 + ((size_t)(n * HH + h) * WW) * (CI / 16));
    for (int j = tid; j < WW * (CI / 4); j += 256) {
        int w = j >> 6, c4 = j & 63;            // consecutive j -> consecutive banks
        dst[j] = *(const unsigned*)(s + w * XS_STRIDE + c4 * 4);
    }
}

// sign(M) -> IMMA B-fragment order (validated in R5, rel_err 0).
__global__ void pack_wf_kernel(const float* __restrict__ M) {
    int idx = blockIdx.x * blockDim.x + threadIdx.x;
    if (idx >= 72 * 16 * 32) return;
    const int lane  = idx & 31;
    const int grp   = (idx >> 5) & 15;
    const int kstep = idx >> 9;                 // 0..71
    const int tap   = kstep >> 3;
    const int chunk = kstep & 7;
    const int row = lane >> 2, kb = (lane & 3) * 4;
    const int o0 = grp * 16, c0 = chunk * 32;
    char b[16];
#pragma unroll
    for (int j = 0; j < 4; j++) {
        int o = o0 + ((j >> 1) ? 8 : 0) + row;
        int c = c0 + ((j & 1) ? 16 : 0) + kb;
#pragma unroll
        for (int t = 0; t < 4; t++) {
            float v = M[((size_t)o * CI + (c + t)) * NTAP + tap];
            b[j * 4 + t] = (v >= 0.0f) ? (char)1 : (char)-1;
        }
    }
    g_Wf4[idx] = *(const uint4*)b;
}

// ---------------- main IMMA conv kernel ----------------
// Block: (row-pair bx, image n, o-quarter bz). M=128 (2 rows x 64 padded cols),
// N=64. 8 warps: warp_m=wid&3 (32-px M slice), warp_n=wid>>2 (32-o N slice).
// Warp tile 32M x 32N -> d = 32 regs (spill-free).
#define A_COL_STRIDE 272                        // 256 ch + 16 pad
#define A_TILE_BYTES (4 * 72 * A_COL_STRIDE)    // 78,336
#define SMEM_BYTES   A_TILE_BYTES

extern __shared__ __align__(16) char smem[];

#define IMMA(d, a, b0, b1)                                                      \
    asm volatile("mma.sync.aligned.m16n8k32.row.col.s32.s8.s8.s32 "             \
        "{%0,%1,%2,%3}, {%4,%5,%6,%7}, {%8,%9}, {%0,%1,%2,%3};"                 \
        : "+r"((d)[0]), "+r"((d)[1]), "+r"((d)[2]), "+r"((d)[3])                \
        : "r"((a)[0]), "r"((a)[1]), "r"((a)[2]), "r"((a)[3]), "r"(b0), "r"(b1))

__global__ __launch_bounds__(256, 2)
void bconv_imma_kernel(const float* __restrict__ alpha, float* __restrict__ out) {
    const int tid = threadIdx.x, lane = tid & 31, wid = tid >> 5;
    const int warp_m = wid & 3, warp_n = wid >> 2;
    const int n = blockIdx.y, h0 = blockIdx.x * 2, bz = blockIdx.z;
    const uint32_t sA = smem_u32(smem);

    // zero A tile (covers padding), then fill valid region
    for (int i = tid; i < A_TILE_BYTES / 16; i += 256)
        ((uint4*)smem)[i] = make_uint4(0, 0, 0, 0);
    __syncthreads();
    for (int i = tid; i < 4 * WW * (CI / 16); i += 256) {
        int u  = i & 15;
        int iw = (i >> 4) % WW;
        int rp = i / (16 * WW);                 // 0..3
        int h  = h0 - 1 + rp;
        if (h >= 0 && h < HH) {
            uint4 v = g_A4[((size_t)(n * HH + h) * WW + iw) * 16 + u];
            *(uint4*)(smem + (rp * 72 + iw + 1) * A_COL_STRIDE + u * 16) = v;
        }
    }
    __syncthreads();

    const int rowq = warp_m >> 1;               // output row within pair
    const int colb = (warp_m & 1) * 32;         // col base of this warp's 32 px

    // ---- main K loop: 72 k-steps (9 taps x 8 ch-chunks) ----
    const uint4* pB = g_Wf4 + (bz * 4 + warp_n * 2) * 32 + lane;
    uint4 bc0 = pB[0], bc1 = pB[32];
    uint32_t ab0 = 0, ab1 = 0;
    int d[8][4];
#pragma unroll
    for (int t = 0; t < 8; t++)
#pragma unroll
        for (int c = 0; c < 4; c++) d[t][c] = 0;

#pragma unroll 1
    for (int k = 0; k < 72; k++) {
        const int tap = k >> 3, ch = k & 7;
        if (ch == 0) {
            const int dy  = tap / 3 - 1;
            const int dxp = tap % 3;            // dx + 1
            const uint32_t base = sA +
                (uint32_t)(((rowq + dy + 1) * 72 + colb + (lane & 15) + dxp) * A_COL_STRIDE) +
                ((lane >> 4) << 4);
            ab0 = base;
            ab1 = base + 16 * A_COL_STRIDE;
        }
        // prefetch next B frags
        uint4 bn0 = bc0, bn1 = bc1;
        if (k < 71) { bn0 = pB[(k + 1) * 512]; bn1 = pB[(k + 1) * 512 + 32]; }

        uint32_t a0[4], a1[4];
        asm volatile("ldmatrix.sync.aligned.m8n8.x4.shared.b16 {%0,%1,%2,%3}, [%4];"
            : "=r"(a0[0]), "=r"(a0[1]), "=r"(a0[2]), "=r"(a0[3]) : "r"(ab0 + ch * 32));
        asm volatile("ldmatrix.sync.aligned.m8n8.x4.shared.b16 {%0,%1,%2,%3}, [%4];"
            : "=r"(a1[0]), "=r"(a1[1]), "=r"(a1[2]), "=r"(a1[3]) : "r"(ab1 + ch * 32));

        IMMA(d[0], a0, bc0.x, bc0.y);
        IMMA(d[1], a0, bc0.z, bc0.w);
        IMMA(d[2], a0, bc1.x, bc1.y);
        IMMA(d[3], a0, bc1.z, bc1.w);
        IMMA(d[4], a1, bc0.x, bc0.y);
        IMMA(d[5], a1, bc0.z, bc0.w);
        IMMA(d[6], a1, bc1.x, bc1.y);
        IMMA(d[7], a1, bc1.z, bc1.w);
        bc0 = bn0; bc1 = bn1;
    }

    // ---- epilogue: transpose via smem (reuse A tile), coalesced stores ----
    __syncthreads();                            // all warps done reading A tile
    float* sw = (float*)smem + wid * (32 * 33); // 4,224 B per warp
#pragma unroll
    for (int t = 0; t < 2; t++)
#pragma unroll
        for (int j = 0; j < 4; j++)
#pragma unroll
            for (int c = 0; c < 4; c++) {
                int wl = t * 16 + (lane >> 2) + ((c & 2) ? 8 : 0);
                int ol = j * 8 + (lane & 3) * 2 + (c & 1);
                sw[ol * 33 + wl] = (float)d[t * 4 + j][c];
            }
    __syncwarp();

    const int h   = h0 + rowq;
    const int og0 = bz * 64 + warp_n * 32;
    const int w   = colb + lane;
    if (w < WW) {
        for (int ol = 0; ol < 32; ol++) {
            float av = __ldg(&alpha[og0 + ol]);
            out[((size_t)(n * CO + og0 + ol)) * HWSZ + (size_t)h * WW + w] =
                av * sw[ol * 33 + lane];
        }
    }
}

// ---------------- launch ----------------
extern "C" void kernel_launch(void* const* d_in, const int* in_sizes, int n_in,
                              void* d_out, int out_size) {
    const float* x     = (const float*)d_in[0];   // (32,256,56,56)
    const float* M     = (const float*)d_in[1];   // (256,256,3,3)
    const float* alpha = (const float*)d_in[2];   // (256,1,1)
    float* out         = (float*)d_out;           // (32,256,56,56)

    static bool attr_set = false;
    if (!attr_set) {
        cudaFuncSetAttribute(bconv_imma_kernel,
                             cudaFuncAttributeMaxDynamicSharedMemorySize, SMEM_BYTES);
        attr_set = true;
    }

    pack_x_kernel<<<dim3(HH, NB), 256>>>(x);
    pack_wf_kernel<<<(72 * 16 * 32 + 255) / 256, 256>>>(M);
    bconv_imma_kernel<<<dim3(HH / 2, NB, 4), 256, SMEM_BYTES>>>(alpha, out);
}

// round 7
// speedup vs baseline: 2.3569x; 2.1956x over previous
#include <cuda_runtime.h>
#include <cstdint>

// Problem constants
#define NB   32      // batch
#define CI   256     // in channels
#define CO   256     // out channels
#define HH   56
#define WW   56
#define HWSZ (HH*WW)       // 3136
#define CW   8             // 256 ch / 32 bits
#define NTAP 9

// Scratch (device globals; no allocation allowed)
__device__ unsigned g_Apk[NB * CW * HWSZ];      // packed activations [n][cw][h][w]
__device__ unsigned g_Wpk[CO * NTAP * CW];      // packed weights    [o][tap][cw]
__device__ int      g_PW [CO * NTAP];           // per (o,tap) popcount of weight bits

// ---------------------------------------------------------------------------
// Pack activations: bit c set iff x[n][cw*32+c][h][w] >= 0
__global__ void pack_x_kernel(const float* __restrict__ x) {
    int idx = blockIdx.x * blockDim.x + threadIdx.x;
    if (idx >= NB * CW * HWSZ) return;
    int hw = idx % HWSZ;
    int t  = idx / HWSZ;
    int cw = t % CW;
    int n  = t / CW;
    const float* xp = x + ((size_t)(n * CI + cw * 32)) * HWSZ + hw;
    unsigned bits = 0;
#pragma unroll
    for (int c = 0; c < 32; c++) {
        bits |= (xp[(size_t)c * HWSZ] >= 0.0f ? 1u : 0u) << c;
    }
    g_Apk[idx] = bits;
}

// ---------------------------------------------------------------------------
// Pack weights: word (o,tap,cw); bit c set iff M[o][cw*32+c][tap] >= 0
__global__ void pack_w_kernel(const float* __restrict__ M) {
    int idx = blockIdx.x * blockDim.x + threadIdx.x;
    if (idx >= CO * NTAP * CW) return;
    int cw  = idx % CW;
    int t   = idx / CW;
    int tap = t % NTAP;
    int o   = t / NTAP;
    unsigned bits = 0;
#pragma unroll
    for (int c = 0; c < 32; c++) {
        float v = M[((size_t)(o * CI + cw * 32 + c)) * NTAP + tap];
        bits |= (v >= 0.0f ? 1u : 0u) << c;
    }
    g_Wpk[idx] = bits;
}

// Per (o,tap) total weight popcount (for border correction)
__global__ void pw_kernel() {
    int idx = blockIdx.x * blockDim.x + threadIdx.x;
    if (idx >= CO * NTAP) return;
    int s = 0;
#pragma unroll
    for (int cw = 0; cw < CW; cw++) s += __popc(g_Wpk[idx * CW + cw]);
    g_PW[idx] = s;
}

// ---------------------------------------------------------------------------
// Main conv.
//  grid = (HH/TH, NB, NZ); block: 4-row tile of one image, 64 o-channels.
//  One barrier per block. Accumulators: two o-channels packed per 32-bit reg
//  (each half <= 2304 < 2^16) -> 8 acc regs per 16-o group, reg cap 48,
//  6 blocks/SM (42 warps), grid = 2.02 clean waves.
#define TH  4
#define OG  16                 // o-channels per accumulator group (8 packed regs)
#define NZ  4                  // grid.z split of output channels
#define OPB (CO / NZ)          // 64 o-channels per block
#define NTHREADS (WW * TH)     // 224

__global__ __launch_bounds__(NTHREADS, 6)
void bconv_kernel(const float* __restrict__ alpha, float* __restrict__ out) {
    __shared__ __align__(16) unsigned Asm[TH + 2][WW + 2][CW];   // 11,136 B
    __shared__ __align__(16) unsigned Wsm[OPB][NTAP][CW];        // 18,432 B
    __shared__ int   PWsm[OPB][NTAP];                            //  2,304 B
    __shared__ float Alp[OPB];                                   //    256 B

    const int tid    = threadIdx.x;
    const int h0     = blockIdx.x * TH;
    const int n      = blockIdx.y;
    const int obase0 = blockIdx.z * OPB;

    // --- stage activation tile (zero-padded) ---
    const int SITES = (TH + 2) * (WW + 2);          // 348
    for (int i = tid; i < CW * SITES; i += NTHREADS) {
        int cw  = i / SITES;
        int s   = i % SITES;
        int row = s / (WW + 2);
        int col = s % (WW + 2);
        int gh  = h0 - 1 + row;
        int gw  = col - 1;
        unsigned v = 0;
        if (gh >= 0 && gh < HH && gw >= 0 && gw < WW)
            v = g_Apk[(n * CW + cw) * HWSZ + gh * WW + gw];
        Asm[row][col][cw] = v;
    }
    // --- stage weights for this block's 64 o-channels ---
    for (int i = tid; i < OPB * NTAP * CW; i += NTHREADS)
        ((unsigned*)Wsm)[i] = g_Wpk[obase0 * NTAP * CW + i];
    for (int i = tid; i < OPB * NTAP; i += NTHREADS)
        ((int*)PWsm)[i] = g_PW[obase0 * NTAP + i];
    for (int i = tid; i < OPB; i += NTHREADS)
        Alp[i] = alpha[obase0 + i];

    __syncthreads();   // the ONLY barrier in this kernel

    const int tx = tid % WW;        // w
    const int ty = tid / WW;        // 0..3
    const int h  = h0 + ty;
    const int w  = tx;

    const int nrows = 1 + (h > 0) + (h < HH - 1);
    const int ncols = 1 + (w > 0) + (w < WW - 1);
    const int nv    = nrows * ncols;
    const int hw    = h * WW + w;
    const bool border = (nv != 9);

#pragma unroll 1
    for (int og = 0; og < OPB / OG; og++) {
        const int olocal = og * OG;

        unsigned accP[OG / 2];          // lo 16 bits: even o; hi 16 bits: odd o
#pragma unroll
        for (int p = 0; p < OG / 2; p++) accP[p] = 0;

#pragma unroll 1
        for (int tap = 0; tap < NTAP; tap++) {
            const int dy = tap / 3;
            const int dx = tap - dy * 3;
            const uint4* ap = (const uint4*)&Asm[ty + dy][tx + dx][0];
            const uint4 a0 = ap[0];
            const uint4 a1 = ap[1];
#pragma unroll
            for (int p = 0; p < OG / 2; p++) {
                const uint4* we = (const uint4*)&Wsm[olocal + 2 * p][tap][0];
                const uint4 e0 = we[0];
                const uint4 e1 = we[1];
                int se = (__popc(a0.x ^ e0.x) + __popc(a0.y ^ e0.y))
                       + (__popc(a0.z ^ e0.z) + __popc(a0.w ^ e0.w))
                       + (__popc(a1.x ^ e1.x) + __popc(a1.y ^ e1.y))
                       + (__popc(a1.z ^ e1.z) + __popc(a1.w ^ e1.w));
                const uint4* wo = (const uint4*)&Wsm[olocal + 2 * p + 1][tap][0];
                const uint4 o0 = wo[0];
                const uint4 o1 = wo[1];
                int so = (__popc(a0.x ^ o0.x) + __popc(a0.y ^ o0.y))
                       + (__popc(a0.z ^ o0.z) + __popc(a0.w ^ o0.w))
                       + (__popc(a1.x ^ o1.x) + __popc(a1.y ^ o1.y))
                       + (__popc(a1.z ^ o1.z) + __popc(a1.w ^ o1.w));
                // packed accumulate: IMAD (fma pipe) + IADD
                accP[p] += (unsigned)(se + (so << 16));
            }
        }

        // write outputs (border correction only when needed)
#pragma unroll
        for (int p = 0; p < OG / 2; p++) {
            const int oE = olocal + 2 * p;
            const int oO = oE + 1;
            int accE = (int)(accP[p] & 0xFFFFu);
            int accO = (int)(accP[p] >> 16);
            int corrE = 0, corrO = 0;
            if (border) {
#pragma unroll
                for (int tap = 0; tap < NTAP; tap++) {
                    int dy = tap / 3 - 1, dx = tap % 3 - 1;
                    int gh = h + dy, gw = w + dx;
                    if (!(gh >= 0 && gh < HH && gw >= 0 && gw < WW)) {
                        corrE += PWsm[oE][tap];
                        corrO += PWsm[oO][tap];
                    }
                }
            }
            const size_t baseE = ((size_t)(n * CO + obase0 + oE)) * HWSZ + hw;
            out[baseE]        = Alp[oE] * (float)(nv * 256 - 2 * accE + 2 * corrE);
            out[baseE + HWSZ] = Alp[oO] * (float)(nv * 256 - 2 * accO + 2 * corrO);
        }
    }
}

// ---------------------------------------------------------------------------
extern "C" void kernel_launch(void* const* d_in, const int* in_sizes, int n_in,
                              void* d_out, int out_size) {
    const float* x     = (const float*)d_in[0];   // (32,256,56,56)
    const float* M     = (const float*)d_in[1];   // (256,256,3,3)
    const float* alpha = (const float*)d_in[2];   // (256,1,1)
    float* out         = (float*)d_out;           // (32,256,56,56)

    {
        int total = NB * CW * HWSZ;               // 802816
        pack_x_kernel<<<(total + 255) / 256, 256>>>(x);
    }
    {
        int total = CO * NTAP * CW;               // 18432
        pack_w_kernel<<<(total + 127) / 128, 128>>>(M);
    }
    {
        int total = CO * NTAP;                    // 2304
        pw_kernel<<<(total + 127) / 128, 128>>>();
    }
    {
        dim3 grid(HH / TH, NB, NZ);               // (14, 32, 4) = 1792 blocks
        bconv_kernel<<<grid, NTHREADS>>>(alpha, out);
    }
}

// round 8
// speedup vs baseline: 2.6179x; 1.1108x over previous
#include <cuda_runtime.h>
#include <cstdint>

// Problem constants
#define NB   32      // batch
#define CI   256     // in channels
#define CO   256     // out channels
#define HH   56
#define WW   56
#define HWSZ (HH*WW)       // 3136
#define CW   8             // 256 ch / 32 bits
#define NTAP 9

// Scratch (device globals; no allocation allowed)
__device__ unsigned g_Apk[NB * CW * HWSZ];      // packed activations [n][cw][h][w]
__device__ unsigned g_Wpk[CO * NTAP * CW];      // packed weights    [o][tap][cw]
__device__ int      g_PW [CO * NTAP];           // per (o,tap) popcount of weight bits

// ---------------------------------------------------------------------------
__device__ __forceinline__ unsigned lop3_96(unsigned a, unsigned b, unsigned c) {
    unsigned r;
    asm("lop3.b32 %0, %1, %2, %3, 0x96;" : "=r"(r) : "r"(a), "r"(b), "r"(c));
    return r;   // a ^ b ^ c
}
__device__ __forceinline__ unsigned lop3_e8(unsigned a, unsigned b, unsigned c) {
    unsigned r;
    asm("lop3.b32 %0, %1, %2, %3, 0xE8;" : "=r"(r) : "r"(a), "r"(b), "r"(c));
    return r;   // majority(a,b,c)
}
// carry-save adder: 2*h + l == a + b + c (bitwise)
#define CSA(h, l, a, b, c) do { unsigned _x=(a),_y=(b),_z=(c); \
    (h) = lop3_e8(_x,_y,_z); (l) = lop3_96(_x,_y,_z); } while (0)

// ---------------------------------------------------------------------------
// Pack activations: bit c set iff x[n][cw*32+c][h][w] >= 0
__global__ void pack_x_kernel(const float* __restrict__ x) {
    int idx = blockIdx.x * blockDim.x + threadIdx.x;
    if (idx >= NB * CW * HWSZ) return;
    int hw = idx % HWSZ;
    int t  = idx / HWSZ;
    int cw = t % CW;
    int n  = t / CW;
    const float* xp = x + ((size_t)(n * CI + cw * 32)) * HWSZ + hw;
    unsigned bits = 0;
#pragma unroll
    for (int c = 0; c < 32; c++) {
        bits |= (xp[(size_t)c * HWSZ] >= 0.0f ? 1u : 0u) << c;
    }
    g_Apk[idx] = bits;
}

// Pack weights: word (o,tap,cw); bit c set iff M[o][cw*32+c][tap] >= 0
__global__ void pack_w_kernel(const float* __restrict__ M) {
    int idx = blockIdx.x * blockDim.x + threadIdx.x;
    if (idx >= CO * NTAP * CW) return;
    int cw  = idx % CW;
    int t   = idx / CW;
    int tap = t % NTAP;
    int o   = t / NTAP;
    unsigned bits = 0;
#pragma unroll
    for (int c = 0; c < 32; c++) {
        float v = M[((size_t)(o * CI + cw * 32 + c)) * NTAP + tap];
        bits |= (v >= 0.0f ? 1u : 0u) << c;
    }
    g_Wpk[idx] = bits;
}

// Per (o,tap) total weight popcount (for border correction)
__global__ void pw_kernel() {
    int idx = blockIdx.x * blockDim.x + threadIdx.x;
    if (idx >= CO * NTAP) return;
    int s = 0;
#pragma unroll
    for (int cw = 0; cw < CW; cw++) s += __popc(g_Wpk[idx * CW + cw]);
    g_PW[idx] = s;
}

// ---------------------------------------------------------------------------
// Main conv. grid = (HH/TH, NB, NZ); block: 4-row tile, 64 o-channels.
// Harley-Seal CSA popcount: per (px,o), 72 XOR words reduced with
// ones/twos/fours carry-save state across taps; 1 POPC per tap (eights)
// + 3 final POPCs instead of 72 POPCs.
#define TH  4
#define OG  4                  // o-channels processed concurrently (CSA state)
#define NZ  4                  // grid.z split of output channels
#define OPB (CO / NZ)          // 64 o-channels per block
#define NTHREADS (WW * TH)     // 224

__global__ __launch_bounds__(NTHREADS, 5)
void bconv_kernel(const float* __restrict__ alpha, float* __restrict__ out) {
    __shared__ __align__(16) unsigned Asm[TH + 2][WW + 2][CW];   // 11,136 B
    __shared__ __align__(16) unsigned Wsm[OPB][NTAP][CW];        // 18,432 B
    __shared__ int   PWsm[OPB][NTAP];                            //  2,304 B
    __shared__ float Alp[OPB];                                   //    256 B

    const int tid    = threadIdx.x;
    const int h0     = blockIdx.x * TH;
    const int n      = blockIdx.y;
    const int obase0 = blockIdx.z * OPB;

    // --- stage activation tile (zero-padded) ---
    const int SITES = (TH + 2) * (WW + 2);          // 348
    for (int i = tid; i < CW * SITES; i += NTHREADS) {
        int cw  = i / SITES;
        int s   = i % SITES;
        int row = s / (WW + 2);
        int col = s % (WW + 2);
        int gh  = h0 - 1 + row;
        int gw  = col - 1;
        unsigned v = 0;
        if (gh >= 0 && gh < HH && gw >= 0 && gw < WW)
            v = g_Apk[(n * CW + cw) * HWSZ + gh * WW + gw];
        Asm[row][col][cw] = v;
    }
    // --- stage weights for this block's 64 o-channels ---
    for (int i = tid; i < OPB * NTAP * CW; i += NTHREADS)
        ((unsigned*)Wsm)[i] = g_Wpk[obase0 * NTAP * CW + i];
    for (int i = tid; i < OPB * NTAP; i += NTHREADS)
        ((int*)PWsm)[i] = g_PW[obase0 * NTAP + i];
    for (int i = tid; i < OPB; i += NTHREADS)
        Alp[i] = alpha[obase0 + i];

    __syncthreads();   // the ONLY barrier in this kernel

    const int tx = tid % WW;        // w
    const int ty = tid / WW;        // 0..3
    const int h  = h0 + ty;
    const int w  = tx;

    const int nrows = 1 + (h > 0) + (h < HH - 1);
    const int ncols = 1 + (w > 0) + (w < WW - 1);
    const int nv    = nrows * ncols;
    const int hw    = h * WW + w;
    const bool border = (nv != 9);

#pragma unroll 1
    for (int og = 0; og < OPB / OG; og++) {
        const int ob = og * OG;

        unsigned ones[OG], twos[OG], fours[OG];
        int acc8[OG];
#pragma unroll
        for (int j = 0; j < OG; j++) { ones[j] = 0; twos[j] = 0; fours[j] = 0; acc8[j] = 0; }

#pragma unroll
        for (int tap = 0; tap < NTAP; tap++) {
            const int dy = tap / 3;
            const int dx = tap - dy * 3;
            const uint4* ap = (const uint4*)&Asm[ty + dy][tx + dx][0];
            const uint4 a0 = ap[0];
            const uint4 a1 = ap[1];
#pragma unroll
            for (int j = 0; j < OG; j++) {
                const uint4* wp = (const uint4*)&Wsm[ob + j][tap][0];
                const uint4 w0 = wp[0];
                const uint4 w1 = wp[1];
                const unsigned d0 = a0.x ^ w0.x, d1 = a0.y ^ w0.y;
                const unsigned d2 = a0.z ^ w0.z, d3 = a0.w ^ w0.w;
                const unsigned d4 = a1.x ^ w1.x, d5 = a1.y ^ w1.y;
                const unsigned d6 = a1.z ^ w1.z, d7 = a1.w ^ w1.w;
                unsigned ta, tb, fa, fb, eig;
                CSA(ta, ones[j], ones[j], d0, d1);
                CSA(tb, ones[j], ones[j], d2, d3);
                CSA(fa, twos[j], twos[j], ta, tb);
                CSA(ta, ones[j], ones[j], d4, d5);
                CSA(tb, ones[j], ones[j], d6, d7);
                CSA(fb, twos[j], twos[j], ta, tb);
                CSA(eig, fours[j], fours[j], fa, fb);
                acc8[j] += __popc(eig);
            }
        }

        // finalize + write outputs (border correction only when needed)
#pragma unroll
        for (int j = 0; j < OG; j++) {
            const int o = ob + j;
            int acc = (acc8[j] << 3) + (__popc(fours[j]) << 2)
                    + (__popc(twos[j]) << 1) + __popc(ones[j]);
            int corr = 0;
            if (border) {
#pragma unroll
                for (int tap = 0; tap < NTAP; tap++) {
                    int dy = tap / 3 - 1, dx = tap % 3 - 1;
                    int gh = h + dy, gw = w + dx;
                    if (!(gh >= 0 && gh < HH && gw >= 0 && gw < WW))
                        corr += PWsm[o][tap];
                }
            }
            out[((size_t)(n * CO + obase0 + o)) * HWSZ + hw] =
                Alp[o] * (float)(nv * 256 - 2 * acc + 2 * corr);
        }
    }
}

// ---------------------------------------------------------------------------
extern "C" void kernel_launch(void* const* d_in, const int* in_sizes, int n_in,
                              void* d_out, int out_size) {
    const float* x     = (const float*)d_in[0];   // (32,256,56,56)
    const float* M     = (const float*)d_in[1];   // (256,256,3,3)
    const float* alpha = (const float*)d_in[2];   // (256,1,1)
    float* out         = (float*)d_out;           // (32,256,56,56)

    {
        int total = NB * CW * HWSZ;               // 802816
        pack_x_kernel<<<(total + 255) / 256, 256>>>(x);
    }
    {
        int total = CO * NTAP * CW;               // 18432
        pack_w_kernel<<<(total + 127) / 128, 128>>>(M);
    }
    {
        int total = CO * NTAP;                    // 2304
        pw_kernel<<<(total + 127) / 128, 128>>>();
    }
    {
        dim3 grid(HH / TH, NB, NZ);               // (14, 32, 4) = 1792 blocks
        bconv_kernel<<<grid, NTHREADS>>>(alpha, out);
    }
}

// round 9
// speedup vs baseline: 2.6747x; 1.0217x over previous
#include <cuda_runtime.h>
#include <cstdint>

// Problem constants
#define NB   32      // batch
#define CI   256     // in channels
#define CO   256     // out channels
#define HH   56
#define WW   56
#define HWSZ (HH*WW)       // 3136
#define CW   8             // 256 ch / 32 bits
#define NTAP 9

// Scratch (device globals; no allocation allowed)
__device__ unsigned g_Apk[NB * CW * HWSZ];      // packed activations [n][cw][h][w]
__device__ unsigned g_Wpk[CO * NTAP * CW];      // packed weights    [o][tap][cw]
__device__ int      g_PW [CO * NTAP];           // per (o,tap) popcount of weight bits

// ---------------------------------------------------------------------------
__device__ __forceinline__ unsigned lop3_96(unsigned a, unsigned b, unsigned c) {
    unsigned r;
    asm("lop3.b32 %0, %1, %2, %3, 0x96;" : "=r"(r) : "r"(a), "r"(b), "r"(c));
    return r;   // a ^ b ^ c
}
__device__ __forceinline__ unsigned lop3_e8(unsigned a, unsigned b, unsigned c) {
    unsigned r;
    asm("lop3.b32 %0, %1, %2, %3, 0xE8;" : "=r"(r) : "r"(a), "r"(b), "r"(c));
    return r;   // majority(a,b,c)
}
// carry-save adder: 2*h + l == a + b + c (bitwise)
#define CSA(h, l, a, b, c) do { unsigned _x=(a),_y=(b),_z=(c); \
    (h) = lop3_e8(_x,_y,_z); (l) = lop3_96(_x,_y,_z); } while (0)

// ---------------------------------------------------------------------------
// Pack activations: bit c set iff x[n][cw*32+c][h][w] >= 0
__global__ void pack_x_kernel(const float* __restrict__ x) {
    int idx = blockIdx.x * blockDim.x + threadIdx.x;
    if (idx >= NB * CW * HWSZ) return;
    int hw = idx % HWSZ;
    int t  = idx / HWSZ;
    int cw = t % CW;
    int n  = t / CW;
    const float* xp = x + ((size_t)(n * CI + cw * 32)) * HWSZ + hw;
    unsigned bits = 0;
#pragma unroll
    for (int c = 0; c < 32; c++) {
        bits |= (xp[(size_t)c * HWSZ] >= 0.0f ? 1u : 0u) << c;
    }
    g_Apk[idx] = bits;
}

// Pack weights: word (o,tap,cw); bit c set iff M[o][cw*32+c][tap] >= 0
__global__ void pack_w_kernel(const float* __restrict__ M) {
    int idx = blockIdx.x * blockDim.x + threadIdx.x;
    if (idx >= CO * NTAP * CW) return;
    int cw  = idx % CW;
    int t   = idx / CW;
    int tap = t % NTAP;
    int o   = t / NTAP;
    unsigned bits = 0;
#pragma unroll
    for (int c = 0; c < 32; c++) {
        float v = M[((size_t)(o * CI + cw * 32 + c)) * NTAP + tap];
        bits |= (v >= 0.0f ? 1u : 0u) << c;
    }
    g_Wpk[idx] = bits;
}

// Per (o,tap) total weight popcount (for border correction)
__global__ void pw_kernel() {
    int idx = blockIdx.x * blockDim.x + threadIdx.x;
    if (idx >= CO * NTAP) return;
    int s = 0;
#pragma unroll
    for (int cw = 0; cw < CW; cw++) s += __popc(g_Wpk[idx * CW + cw]);
    g_PW[idx] = s;
}

// ---------------------------------------------------------------------------
// Main conv. grid = (HH/TH, NB, NZ); block: 4-row tile, 64 o-channels.
// Harley-Seal CSA popcount + conflict-free A layout: the A tile is stored as
// two uint4 PLANES (channels 0-3 and 4-7), so lane stride is 16 B and a warp's
// a-load covers 512 contiguous bytes = minimal 4 crossbar phases, 0 conflicts.
#define TH  4
#define OG  4                  // o-channels processed concurrently (CSA state)
#define NZ  4                  // grid.z split of output channels
#define OPB (CO / NZ)          // 64 o-channels per block
#define NTHREADS (WW * TH)     // 224

__global__ __launch_bounds__(NTHREADS, 5)
void bconv_kernel(const float* __restrict__ alpha, float* __restrict__ out) {
    __shared__ __align__(16) uint4 Asm0[TH + 2][WW + 2];         // 9,280 B
    __shared__ __align__(16) uint4 Asm1[TH + 2][WW + 2];         // 9,280 B
    __shared__ __align__(16) unsigned Wsm[OPB][NTAP][CW];        // 18,432 B
    __shared__ int   PWsm[OPB][NTAP];                            //  2,304 B
    __shared__ float Alp[OPB];                                   //    256 B

    const int tid    = threadIdx.x;
    const int h0     = blockIdx.x * TH;
    const int n      = blockIdx.y;
    const int obase0 = blockIdx.z * OPB;

    // --- stage activation tile (zero-padded), vectorized per plane ---
    const int SITES = (TH + 2) * (WW + 2);          // 348
    for (int i = tid; i < 2 * SITES; i += NTHREADS) {
        int u   = i / SITES;                        // plane: ch words 4u..4u+3
        int s   = i % SITES;
        int row = s / (WW + 2);
        int col = s % (WW + 2);
        int gh  = h0 - 1 + row;
        int gw  = col - 1;
        uint4 v = make_uint4(0, 0, 0, 0);
        if (gh >= 0 && gh < HH && gw >= 0 && gw < WW) {
            const unsigned* gp = &g_Apk[(n * CW + u * 4) * HWSZ + gh * WW + gw];
            v.x = gp[0];
            v.y = gp[HWSZ];
            v.z = gp[2 * HWSZ];
            v.w = gp[3 * HWSZ];
        }
        if (u == 0) Asm0[row][col] = v; else Asm1[row][col] = v;
    }
    // --- stage weights for this block's 64 o-channels ---
    for (int i = tid; i < OPB * NTAP * CW; i += NTHREADS)
        ((unsigned*)Wsm)[i] = g_Wpk[obase0 * NTAP * CW + i];
    for (int i = tid; i < OPB * NTAP; i += NTHREADS)
        ((int*)PWsm)[i] = g_PW[obase0 * NTAP + i];
    for (int i = tid; i < OPB; i += NTHREADS)
        Alp[i] = alpha[obase0 + i];

    __syncthreads();   // the ONLY barrier in this kernel

    const int tx = tid % WW;        // w
    const int ty = tid / WW;        // 0..3
    const int h  = h0 + ty;
    const int w  = tx;

    const int nrows = 1 + (h > 0) + (h < HH - 1);
    const int ncols = 1 + (w > 0) + (w < WW - 1);
    const int nv    = nrows * ncols;
    const int hw    = h * WW + w;
    const bool border = (nv != 9);

#pragma unroll 1
    for (int og = 0; og < OPB / OG; og++) {
        const int ob = og * OG;

        unsigned ones[OG], twos[OG], fours[OG];
        int acc8[OG];
#pragma unroll
        for (int j = 0; j < OG; j++) { ones[j] = 0; twos[j] = 0; fours[j] = 0; acc8[j] = 0; }

#pragma unroll
        for (int tap = 0; tap < NTAP; tap++) {
            const int dy = tap / 3;
            const int dx = tap - dy * 3;
            const uint4 a0 = Asm0[ty + dy][tx + dx];
            const uint4 a1 = Asm1[ty + dy][tx + dx];
#pragma unroll
            for (int j = 0; j < OG; j++) {
                const uint4* wp = (const uint4*)&Wsm[ob + j][tap][0];
                const uint4 w0 = wp[0];
                const uint4 w1 = wp[1];
                const unsigned d0 = a0.x ^ w0.x, d1 = a0.y ^ w0.y;
                const unsigned d2 = a0.z ^ w0.z, d3 = a0.w ^ w0.w;
                const unsigned d4 = a1.x ^ w1.x, d5 = a1.y ^ w1.y;
                const unsigned d6 = a1.z ^ w1.z, d7 = a1.w ^ w1.w;
                unsigned ta, tb, fa, fb, eig;
                CSA(ta, ones[j], ones[j], d0, d1);
                CSA(tb, ones[j], ones[j], d2, d3);
                CSA(fa, twos[j], twos[j], ta, tb);
                CSA(ta, ones[j], ones[j], d4, d5);
                CSA(tb, ones[j], ones[j], d6, d7);
                CSA(fb, twos[j], twos[j], ta, tb);
                CSA(eig, fours[j], fours[j], fa, fb);
                acc8[j] += __popc(eig);
            }
        }

        // finalize + write outputs (border correction only when needed)
#pragma unroll
        for (int j = 0; j < OG; j++) {
            const int o = ob + j;
            int acc = (acc8[j] << 3) + (__popc(fours[j]) << 2)
                    + (__popc(twos[j]) << 1) + __popc(ones[j]);
            int corr = 0;
            if (border) {
#pragma unroll
                for (int tap = 0; tap < NTAP; tap++) {
                    int dy = tap / 3 - 1, dx = tap % 3 - 1;
                    int gh = h + dy, gw = w + dx;
                    if (!(gh >= 0 && gh < HH && gw >= 0 && gw < WW))
                        corr += PWsm[o][tap];
                }
            }
            out[((size_t)(n * CO + obase0 + o)) * HWSZ + hw] =
                Alp[o] * (float)(nv * 256 - 2 * acc + 2 * corr);
        }
    }
}

// ---------------------------------------------------------------------------
extern "C" void kernel_launch(void* const* d_in, const int* in_sizes, int n_in,
                              void* d_out, int out_size) {
    const float* x     = (const float*)d_in[0];   // (32,256,56,56)
    const float* M     = (const float*)d_in[1];   // (256,256,3,3)
    const float* alpha = (const float*)d_in[2];   // (256,1,1)
    float* out         = (float*)d_out;           // (32,256,56,56)

    {
        int total = NB * CW * HWSZ;               // 802816
        pack_x_kernel<<<(total + 255) / 256, 256>>>(x);
    }
    {
        int total = CO * NTAP * CW;               // 18432
        pack_w_kernel<<<(total + 127) / 128, 128>>>(M);
    }
    {
        int total = CO * NTAP;                    // 2304
        pw_kernel<<<(total + 127) / 128, 128>>>();
    }
    {
        dim3 grid(HH / TH, NB, NZ);               // (14, 32, 4) = 1792 blocks
        bconv_kernel<<<grid, NTHREADS>>>(alpha, out);
    }
}